// round 3
// baseline (speedup 1.0000x reference)
#include <cuda_runtime.h>

#define NN 8192
#define FIN 512
#define FF 256
#define ALPHA 0.2f

// Scratch (allocation-free rule: __device__ globals)
__device__ float g_h[NN * FF];     // 8 MB
__device__ float g_s1[NN];
__device__ float g_s2[NN];

// ---------------------------------------------------------------------------
// Kernel 1: h = X @ W   (8192x512 @ 512x256)
// Block = 256 threads computes 32 rows x 256 cols (full width).
// K staged in 32-wide tiles in smem (layout Xs[k][r], stride 36 for float4
// broadcast reads).
// ---------------------------------------------------------------------------
__global__ __launch_bounds__(256) void gemm_xw(const float* __restrict__ X,
                                               const float* __restrict__ W) {
    __shared__ float Xs[32 * 36];
    const int t = threadIdx.x;
    const int i0 = blockIdx.x * 32;
    const int c = t;  // output column

    float acc[32];
#pragma unroll
    for (int r = 0; r < 32; r++) acc[r] = 0.f;

    const int kk = t & 31;
    const int rb = t >> 5;

    for (int k0 = 0; k0 < FIN; k0 += 32) {
#pragma unroll
        for (int q = 0; q < 4; q++) {
            int r = rb + 8 * q;
            Xs[kk * 36 + r] = X[(i0 + r) * FIN + k0 + kk];
        }
        __syncthreads();
#pragma unroll
        for (int k = 0; k < 32; k++) {
            float wv = W[(k0 + k) * FF + c];
            const float4* xp = reinterpret_cast<const float4*>(&Xs[k * 36]);
#pragma unroll
            for (int u = 0; u < 8; u++) {
                float4 xv = xp[u];
                acc[4 * u + 0] = fmaf(xv.x, wv, acc[4 * u + 0]);
                acc[4 * u + 1] = fmaf(xv.y, wv, acc[4 * u + 1]);
                acc[4 * u + 2] = fmaf(xv.z, wv, acc[4 * u + 2]);
                acc[4 * u + 3] = fmaf(xv.w, wv, acc[4 * u + 3]);
            }
        }
        __syncthreads();
    }
#pragma unroll
    for (int r = 0; r < 32; r++) g_h[(i0 + r) * FF + c] = acc[r];
}

// ---------------------------------------------------------------------------
// Kernel 2: s1[i] = h[i,:] . a[0:256],  s2[i] = h[i,:] . a[256:512]
// One warp per row.
// ---------------------------------------------------------------------------
__global__ __launch_bounds__(256) void svec_kernel(const float* __restrict__ a) {
    __shared__ float as[2 * FF];
    const int t = threadIdx.x;
    as[t] = a[t];
    as[t + 256] = a[t + 256];
    __syncthreads();

    const int warp = t >> 5;
    const int lane = t & 31;
    const int row = blockIdx.x * 8 + warp;

    float s1 = 0.f, s2 = 0.f;
#pragma unroll
    for (int q = 0; q < 8; q++) {
        int f = lane + 32 * q;
        float v = g_h[row * FF + f];
        s1 = fmaf(v, as[f], s1);
        s2 = fmaf(v, as[FF + f], s2);
    }
#pragma unroll
    for (int off = 16; off; off >>= 1) {
        s1 += __shfl_xor_sync(0xFFFFFFFFu, s1, off);
        s2 += __shfl_xor_sync(0xFFFFFFFFu, s2, off);
    }
    if (lane == 0) {
        g_s1[row] = s1;
        g_s2[row] = s2;
    }
}

// ---------------------------------------------------------------------------
// Kernel 3: fused masked-softmax attention + P@h + ELU.
// Block = 256 threads handles 32 output rows x 256 features.
// Phase 0: per-row max over neighbors (lrelu is monotone, so
//          max_j masked e_ij = lrelu(s1_i + max_{adj} s2_j); we compute the
//          max of the full e directly for robustness).
// Then loop over 32-wide j chunks:
//   A : P tile (32x32) -> smem, running Z per row in registers
//   A2: stage h chunk (32x256) -> smem
//   B : micro-GEMM: thread owns 8 rows x 4 features (float4)
// Epilogue: scale by 1/Z, ELU, float4 store.
// ---------------------------------------------------------------------------
__global__ __launch_bounds__(256) void gat_main(const int* __restrict__ adj,
                                                float* __restrict__ out) {
    __shared__ float hs[32 * FF];   // 32 KB
    __shared__ float ps[32 * 33];   // P tile, padded stride
    __shared__ float s1s[32];
    __shared__ float ms[32];
    __shared__ float zs[32];

    const int t = threadIdx.x;
    const int i0 = blockIdx.x * 32;
    const int warp = t >> 5;
    const int lane = t & 31;

    if (t < 32) s1s[t] = g_s1[i0 + t];

    // ---- Phase 0: row max over allowed j (each warp handles 4 rows) ----
#pragma unroll
    for (int u = 0; u < 4; u++) {
        const int r = warp * 4 + u;
        const int* arow = adj + (i0 + r) * NN;
        float m = -3.0e38f;
#pragma unroll 4
        for (int jj = lane; jj < NN; jj += 32) {
            int av = arow[jj];
            if (av > 0) m = fmaxf(m, g_s2[jj]);
        }
#pragma unroll
        for (int off = 16; off; off >>= 1)
            m = fmaxf(m, __shfl_xor_sync(0xFFFFFFFFu, m, off));
        if (lane == 0) {
            // convert s2-max to e-max via monotone lrelu; sentinel if no nbrs
            if (m < -1.0e37f) {
                ms[r] = -3.0e38f;
            } else {
                float e = s1s[r] + m;
                ms[r] = fmaxf(e, ALPHA * e);
            }
        }
    }
    __syncthreads();

    float4 acc[8];
#pragma unroll
    for (int u = 0; u < 8; u++) acc[u] = make_float4(0.f, 0.f, 0.f, 0.f);
    float zpart[4] = {0.f, 0.f, 0.f, 0.f};

    const int jlane = t & 31;   // phase-A role: j within chunk
    const int rg = t >> 5;      // phase-A role: row group (4 rows)
    const int fg = t & 63;      // phase-B role: feature group (4 feats)
    const int rg2 = t >> 6;     // phase-B role: row group (8 rows)

    for (int jc = 0; jc < NN; jc += 32) {
        const int jg = jc + jlane;
        const float s2j = g_s2[jg];

        // ---- Phase A: P tile + running Z ----
#pragma unroll
        for (int u = 0; u < 4; u++) {
            const int r = rg * 4 + u;
            const float m = ms[r];
            const int av = adj[(i0 + r) * NN + jg];
            float e = s1s[r] + s2j;
            e = fmaxf(e, ALPHA * e);
            float p;
            if (m < -1.0e37f) {
                p = 1.0f;  // degenerate row: uniform softmax over all j
            } else {
                p = (av > 0) ? __expf(e - m) : 0.0f;
            }
            ps[r * 33 + jlane] = p;
            zpart[u] += p;
        }

        // ---- Phase A2: stage h[jc..jc+31][:] into smem ----
#pragma unroll
        for (int it = 0; it < 8; it++) {
            int idx = t + 256 * it;
            int row = idx >> 6;
            int c4 = (idx & 63) << 2;
            *reinterpret_cast<float4*>(&hs[row * FF + c4]) =
                *reinterpret_cast<const float4*>(&g_h[(jc + row) * FF + c4]);
        }
        __syncthreads();

        // ---- Phase B: acc += P_tile @ h_tile ----
#pragma unroll 8
        for (int j = 0; j < 32; j++) {
            float4 hv = *reinterpret_cast<const float4*>(&hs[j * FF + fg * 4]);
#pragma unroll
            for (int u = 0; u < 8; u++) {
                float p = ps[(rg2 * 8 + u) * 33 + j];
                acc[u].x = fmaf(p, hv.x, acc[u].x);
                acc[u].y = fmaf(p, hv.y, acc[u].y);
                acc[u].z = fmaf(p, hv.z, acc[u].z);
                acc[u].w = fmaf(p, hv.w, acc[u].w);
            }
        }
        __syncthreads();
    }

    // ---- Reduce Z across the 32 j-lanes of each warp ----
#pragma unroll
    for (int u = 0; u < 4; u++) {
        float z = zpart[u];
#pragma unroll
        for (int off = 16; off; off >>= 1)
            z += __shfl_xor_sync(0xFFFFFFFFu, z, off);
        if (lane == 0) zs[rg * 4 + u] = z;
    }
    __syncthreads();

    // ---- Epilogue: 1/Z, ELU, store ----
#pragma unroll
    for (int u = 0; u < 8; u++) {
        const int r = rg2 * 8 + u;
        const float inv = 1.0f / zs[r];
        float4 v;
        v.x = acc[u].x * inv;
        v.y = acc[u].y * inv;
        v.z = acc[u].z * inv;
        v.w = acc[u].w * inv;
        v.x = (v.x > 0.f) ? v.x : (__expf(v.x) - 1.0f);
        v.y = (v.y > 0.f) ? v.y : (__expf(v.y) - 1.0f);
        v.z = (v.z > 0.f) ? v.z : (__expf(v.z) - 1.0f);
        v.w = (v.w > 0.f) ? v.w : (__expf(v.w) - 1.0f);
        *reinterpret_cast<float4*>(&out[(i0 + r) * FF + fg * 4]) = v;
    }
}

// ---------------------------------------------------------------------------
extern "C" void kernel_launch(void* const* d_in, const int* in_sizes, int n_in,
                              void* d_out, int out_size) {
    const float* X = (const float*)d_in[0];     // [8192, 512]
    const int* adj = (const int*)d_in[1];       // [8192, 8192]
    const float* W = (const float*)d_in[2];     // [512, 256]
    const float* a = (const float*)d_in[3];     // [512, 1]
    float* out = (float*)d_out;                 // [8192, 256]

    gemm_xw<<<NN / 32, 256>>>(X, W);
    svec_kernel<<<NN / 8, 256>>>(a);
    gat_main<<<NN / 32, 256>>>(adj, out);
}